// round 14
// baseline (speedup 1.0000x reference)
#include <cuda_runtime.h>

#define H 50
#define BTOT 2048
#define TLEN 1024
#define NBAT 8           // batches per block; grid = 2048/8 = 256 -> 2 CTAs/SM
#define NTH 128          // 4 warps; active threads: j<50 in each 64-group (100)
#define XCH 16
#define GP 12            // hsh row: 12 floats = 48B (odd*16B) -> conflict-light

typedef unsigned long long u64;

__device__ __forceinline__ u64 ffma2n(u64 a, u64 b, u64 c) {
    u64 d; asm("fma.rn.f32x2 %0, %1, %2, %3;" : "=l"(d) : "l"(a), "l"(b), "l"(c)); return d;
}
__device__ __forceinline__ void ffma2(u64 &d, u64 a, u64 b) {
    asm("fma.rn.f32x2 %0, %1, %2, %0;" : "+l"(d) : "l"(a), "l"(b));
}
__device__ __forceinline__ u64 splat2(float x) {
    u64 r; asm("mov.b64 %0, {%1, %1};" : "=l"(r) : "f"(x)); return r;
}
__device__ __forceinline__ void unpack2(u64 v, float &lo, float &hi) {
    asm("mov.b64 {%0, %1}, %2;" : "=f"(lo), "=f"(hi) : "l"(v));
}
__device__ __forceinline__ float tanh_f(float x) {
    float y; asm("tanh.approx.f32 %0, %1;" : "=f"(y) : "f"(x)); return y;
}
__device__ __forceinline__ float sigf(float x) {
    return fmaf(0.5f, tanh_f(0.5f * x), 0.5f);
}

// Fully fused lstm1 (1024 steps) + lstm2 cell + FC.
// grid=256 blocks of 8 batches -> 2 co-resident CTAs per SM. Independent CTA
// barriers let one CTA's MUFU epilogue/barrier tail overlap the other's FMA
// phase (2 warps/SMSP from different CTAs).
// Thread (j = tid&63 [<50 active], bg = tid>>6) computes 4 gates of hidden
// unit j for 4 batches (slots bg*4 .. bg*4+3), pair-packed in f32x2.
__global__ void __launch_bounds__(NTH) fused_lstm_kernel(
    const float* __restrict__ x,
    const float* __restrict__ Wih,
    const float* __restrict__ Whh,
    const float* __restrict__ bih,
    const float* __restrict__ bhh,
    const float* __restrict__ W2ih,
    const float* __restrict__ b2ih,
    const float* __restrict__ b2hh,
    const float* __restrict__ fcW,
    const float* __restrict__ fcb,
    float* __restrict__ out)
{
    __shared__ __align__(16) float4 Wq[H][H];       // [k][j] = (Wi,Wf,Wg,Wo)[j][k]  40000B
    __shared__ __align__(16) float  hsh[2][H][GP];  // double-buffered h              4800B
    __shared__ __align__(16) float  xsh[XCH][NBAT]; // x chunk                        512B

    const int tid = threadIdx.x;
    const int bg  = tid >> 6;        // 0..1
    const int j   = tid & 63;        // active if < 50
    const bool act = j < H;
    const int bbase = blockIdx.x * NBAT;
    const int sl = bg * 4;           // batch slot base (0 or 4)

    // Prepack Whh gate quads: Wq[k][jj] = 4 gate rows at column k
    for (int i = tid; i < H * H; i += NTH) {
        int k = i / H, jj = i - k * H;
        Wq[k][jj] = make_float4(Whh[jj * H + k],
                                Whh[(H + jj) * H + k],
                                Whh[(2 * H + jj) * H + k],
                                Whh[(3 * H + jj) * H + k]);
    }
    for (int i = tid; i < 2 * H * GP; i += NTH)
        (&hsh[0][0][0])[i] = 0.0f;

    u64 bI = 0, bF = 0, bG = 0, bO = 0, wiI = 0, wiF = 0, wiG = 0, wiO = 0;
    if (act) {
        bI = splat2(bih[j]         + bhh[j]);
        bF = splat2(bih[H + j]     + bhh[H + j]);
        bG = splat2(bih[2 * H + j] + bhh[2 * H + j]);
        bO = splat2(bih[3 * H + j] + bhh[3 * H + j]);
        wiI = splat2(Wih[j]);
        wiF = splat2(Wih[H + j]);
        wiG = splat2(Wih[2 * H + j]);
        wiO = splat2(Wih[3 * H + j]);
    }

    float c[4]  = {0.f, 0.f, 0.f, 0.f};
    float hv[4] = {0.f, 0.f, 0.f, 0.f};

    __syncthreads();

    for (int t = 0; t < TLEN; t++) {
        if ((t & (XCH - 1)) == 0) {
            // previous end-of-step barrier guarantees old xsh reads are done
            for (int i = tid; i < XCH * NBAT; i += NTH) {
                int tc = i >> 3, bl = i & 7;
                xsh[tc][bl] = x[(bbase + bl) * TLEN + t + tc];
            }
            __syncthreads();
        }
        const int buf = t & 1;

        if (act) {
            const u64* xp = (const u64*)&xsh[t & (XCH - 1)][sl];
            const u64 x01 = xp[0], x23 = xp[1];

            u64 aI[2], aF[2], aG[2], aO[2];
            aI[0] = ffma2n(x01, wiI, bI); aI[1] = ffma2n(x23, wiI, bI);
            aF[0] = ffma2n(x01, wiF, bF); aF[1] = ffma2n(x23, wiF, bF);
            aG[0] = ffma2n(x01, wiG, bG); aG[1] = ffma2n(x23, wiG, bG);
            aO[0] = ffma2n(x01, wiO, bO); aO[1] = ffma2n(x23, wiO, bO);

#pragma unroll 10
            for (int k = 0; k < H; k++) {
                const float4 w = Wq[k][j];                      // LDS.128
                const u64* hp = (const u64*)&hsh[buf][k][sl];   // broadcast LDS.64 x2
                const u64 h01 = hp[0], h23 = hp[1];
                const u64 wI = splat2(w.x), wF = splat2(w.y);
                const u64 wG = splat2(w.z), wO = splat2(w.w);
                ffma2(aI[0], h01, wI); ffma2(aI[1], h23, wI);
                ffma2(aF[0], h01, wF); ffma2(aF[1], h23, wF);
                ffma2(aG[0], h01, wG); ffma2(aG[1], h23, wG);
                ffma2(aO[0], h01, wO); ffma2(aO[1], h23, wO);
            }

            float ip[4], fp[4], gp[4], op[4];
#pragma unroll
            for (int r = 0; r < 2; r++) {
                unpack2(aI[r], ip[2 * r], ip[2 * r + 1]);
                unpack2(aF[r], fp[2 * r], fp[2 * r + 1]);
                unpack2(aG[r], gp[2 * r], gp[2 * r + 1]);
                unpack2(aO[r], op[2 * r], op[2 * r + 1]);
            }
#pragma unroll
            for (int r = 0; r < 4; r++) {
                const float ig = sigf(ip[r]);
                const float fg = sigf(fp[r]);
                const float gg = tanh_f(gp[r]);
                const float og = sigf(op[r]);
                c[r]  = fmaf(fg, c[r], ig * gg);
                hv[r] = og * tanh_f(c[r]);
            }
            *(float4*)&hsh[buf ^ 1][j][sl] =
                make_float4(hv[0], hv[1], hv[2], hv[3]);
        }
        __syncthreads();
    }
    // Final h1 lives in hsh buffer 0 (t=1023: buf=1, wrote buf^1=0).

    // ---- lstm2 single cell (zero initial state) + FC, fused ----
    for (int i = tid; i < H * H; i += NTH) {
        int k = i / H, jj = i - k * H;
        Wq[k][jj] = make_float4(W2ih[jj * H + k],
                                W2ih[(H + jj) * H + k],
                                W2ih[(2 * H + jj) * H + k],
                                W2ih[(3 * H + jj) * H + k]);
    }
    __syncthreads();

    float* h2s = &hsh[1][0][0];   // buffer 1 free; layout [j][slot], stride GP

    if (act) {
        const u64 cI = splat2(b2ih[j]         + b2hh[j]);
        const u64 cG = splat2(b2ih[2 * H + j] + b2hh[2 * H + j]);
        const u64 cO = splat2(b2ih[3 * H + j] + b2hh[3 * H + j]);
        u64 aI[2] = {cI, cI};
        u64 aG[2] = {cG, cG};
        u64 aO[2] = {cO, cO};   // f-gate skipped: c0 = 0
#pragma unroll 10
        for (int k = 0; k < H; k++) {
            const float4 w = Wq[k][j];
            const u64* hp = (const u64*)&hsh[0][k][sl];
            const u64 h01 = hp[0], h23 = hp[1];
            const u64 wI = splat2(w.x), wG = splat2(w.z), wO = splat2(w.w);
            ffma2(aI[0], h01, wI); ffma2(aI[1], h23, wI);
            ffma2(aG[0], h01, wG); ffma2(aG[1], h23, wG);
            ffma2(aO[0], h01, wO); ffma2(aO[1], h23, wO);
        }
        float ip[4], gp[4], op[4];
#pragma unroll
        for (int r = 0; r < 2; r++) {
            unpack2(aI[r], ip[2 * r], ip[2 * r + 1]);
            unpack2(aG[r], gp[2 * r], gp[2 * r + 1]);
            unpack2(aO[r], op[2 * r], op[2 * r + 1]);
        }
        float h2[4];
#pragma unroll
        for (int r = 0; r < 4; r++) {
            const float ig = sigf(ip[r]);
            const float gg = tanh_f(gp[r]);
            const float og = sigf(op[r]);
            h2[r] = og * tanh_f(ig * gg);   // c = i*g (f*c0 = 0)
        }
        *(float4*)&h2s[j * GP + sl] = make_float4(h2[0], h2[1], h2[2], h2[3]);
    }
    __syncthreads();

    if (tid < NBAT) {
        float s = fcb[0];
#pragma unroll 10
        for (int k = 0; k < H; k++)
            s = fmaf(h2s[k * GP + tid], __ldg(&fcW[k]), s);
        out[bbase + tid] = s;
    }
}

extern "C" void kernel_launch(void* const* d_in, const int* in_sizes, int n_in,
                              void* d_out, int out_size)
{
    const float* x     = (const float*)d_in[0];
    const float* w1ih  = (const float*)d_in[1];
    const float* w1hh  = (const float*)d_in[2];
    const float* b1ih  = (const float*)d_in[3];
    const float* b1hh  = (const float*)d_in[4];
    const float* w2ih  = (const float*)d_in[5];
    // d_in[6] = lstm2_Whh: unused (layer-2 initial state is zero)
    const float* b2ih  = (const float*)d_in[7];
    const float* b2hh  = (const float*)d_in[8];
    const float* fcW   = (const float*)d_in[9];
    const float* fcb   = (const float*)d_in[10];
    float* out = (float*)d_out;

    fused_lstm_kernel<<<BTOT / NBAT, NTH>>>(
        x, w1ih, w1hh, b1ih, b1hh, w2ih, b2ih, b2hh, fcW, fcb, out);
}

// round 16
// speedup vs baseline: 1.5025x; 1.5025x over previous
#include <cuda_runtime.h>

#define H 50
#define BTOT 2048
#define TLEN 1024
#define NBAT 16          // batches per block; grid = 128 -> 1 CTA/SM
#define NTH 256          // 8 warps = 2/SMSP; active: j<50 in each half (200)
#define XCH 16
#define GP 20            // hsh row: 20 floats = 80B (odd*16B) -> conflict-light

typedef unsigned long long u64;

__device__ __forceinline__ u64 ffma2n(u64 a, u64 b, u64 c) {
    u64 d; asm("fma.rn.f32x2 %0, %1, %2, %3;" : "=l"(d) : "l"(a), "l"(b), "l"(c)); return d;
}
__device__ __forceinline__ void ffma2(u64 &d, u64 a, u64 b) {
    asm("fma.rn.f32x2 %0, %1, %2, %0;" : "+l"(d) : "l"(a), "l"(b));
}
__device__ __forceinline__ u64 splat2(float x) {
    u64 r; asm("mov.b64 %0, {%1, %1};" : "=l"(r) : "f"(x)); return r;
}
__device__ __forceinline__ void unpack2(u64 v, float &lo, float &hi) {
    asm("mov.b64 {%0, %1}, %2;" : "=f"(lo), "=f"(hi) : "l"(v));
}
__device__ __forceinline__ float tanh_f(float x) {
    float y; asm("tanh.approx.f32 %0, %1;" : "=f"(y) : "f"(x)); return y;
}
__device__ __forceinline__ float sigf(float x) {
    return fmaf(0.5f, tanh_f(0.5f * x), 0.5f);
}

// Fully fused lstm1 (1024 steps) + lstm2 cell + FC. One CTA/SM, 8 warps.
// Thread mapping: g = tid>>7 (batch octet), lid = tid&127, j = lid>>1
// (active j<50), hb = lid&1 -> batch slots sl = g*8 + hb*4 .. +3.
// Two lanes share each weight quad (16 distinct LDS.128 per warp = 256B) and
// 2 warps/SMSP overlap LDS latency / MUFU epilogue with FMA work.
__global__ void __launch_bounds__(NTH) fused_lstm_kernel(
    const float* __restrict__ x,
    const float* __restrict__ Wih,
    const float* __restrict__ Whh,
    const float* __restrict__ bih,
    const float* __restrict__ bhh,
    const float* __restrict__ W2ih,
    const float* __restrict__ b2ih,
    const float* __restrict__ b2hh,
    const float* __restrict__ fcW,
    const float* __restrict__ fcb,
    float* __restrict__ out)
{
    __shared__ __align__(16) float4 Wq[H][H];       // [k][j] = (Wi,Wf,Wg,Wo)[j][k]  40000B
    __shared__ __align__(16) float  hsh[2][H][GP];  // double-buffered h              8000B
    __shared__ __align__(16) float  xsh[XCH][NBAT]; // x chunk                        1024B

    const int tid = threadIdx.x;
    const int g   = tid >> 7;        // batch octet 0..1
    const int lid = tid & 127;
    const int j   = lid >> 1;        // 0..63, active if < 50
    const int hb  = lid & 1;         // batch half within octet
    const bool act = j < H;
    const int bbase = blockIdx.x * NBAT;
    const int sl = g * 8 + hb * 4;   // batch slot base: 0,4,8,12

    // Prepack Whh gate quads: Wq[k][jj] = 4 gate rows at column k
    for (int i = tid; i < H * H; i += NTH) {
        int k = i / H, jj = i - k * H;
        Wq[k][jj] = make_float4(Whh[jj * H + k],
                                Whh[(H + jj) * H + k],
                                Whh[(2 * H + jj) * H + k],
                                Whh[(3 * H + jj) * H + k]);
    }
    for (int i = tid; i < 2 * H * GP; i += NTH)
        (&hsh[0][0][0])[i] = 0.0f;

    u64 bI = 0, bF = 0, bG = 0, bO = 0, wiI = 0, wiF = 0, wiG = 0, wiO = 0;
    if (act) {
        bI = splat2(bih[j]         + bhh[j]);
        bF = splat2(bih[H + j]     + bhh[H + j]);
        bG = splat2(bih[2 * H + j] + bhh[2 * H + j]);
        bO = splat2(bih[3 * H + j] + bhh[3 * H + j]);
        wiI = splat2(Wih[j]);
        wiF = splat2(Wih[H + j]);
        wiG = splat2(Wih[2 * H + j]);
        wiO = splat2(Wih[3 * H + j]);
    }

    float c[4]  = {0.f, 0.f, 0.f, 0.f};
    float hv[4] = {0.f, 0.f, 0.f, 0.f};

    __syncthreads();

    for (int t = 0; t < TLEN; t++) {
        if ((t & (XCH - 1)) == 0) {
            // previous end-of-step barrier guarantees old xsh reads are done
            {
                int tc = tid >> 4, bl = tid & 15;   // 256 threads = 16x16 exactly
                xsh[tc][bl] = x[(bbase + bl) * TLEN + t + tc];
            }
            __syncthreads();
        }
        const int buf = t & 1;

        if (act) {
            const u64* xp = (const u64*)&xsh[t & (XCH - 1)][sl];
            const u64 x01 = xp[0], x23 = xp[1];

            u64 aI[2], aF[2], aG[2], aO[2];
            aI[0] = ffma2n(x01, wiI, bI); aI[1] = ffma2n(x23, wiI, bI);
            aF[0] = ffma2n(x01, wiF, bF); aF[1] = ffma2n(x23, wiF, bF);
            aG[0] = ffma2n(x01, wiG, bG); aG[1] = ffma2n(x23, wiG, bG);
            aO[0] = ffma2n(x01, wiO, bO); aO[1] = ffma2n(x23, wiO, bO);

#pragma unroll 10
            for (int k = 0; k < H; k++) {
                const float4 w = Wq[k][j];                      // LDS.128, 2 lanes share
                const u64* hp = (const u64*)&hsh[buf][k][sl];   // broadcast LDS.64 x2
                const u64 h01 = hp[0], h23 = hp[1];
                const u64 wI = splat2(w.x), wF = splat2(w.y);
                const u64 wG = splat2(w.z), wO = splat2(w.w);
                ffma2(aI[0], h01, wI); ffma2(aI[1], h23, wI);
                ffma2(aF[0], h01, wF); ffma2(aF[1], h23, wF);
                ffma2(aG[0], h01, wG); ffma2(aG[1], h23, wG);
                ffma2(aO[0], h01, wO); ffma2(aO[1], h23, wO);
            }

            float ip[4], fp[4], gp[4], op[4];
#pragma unroll
            for (int r = 0; r < 2; r++) {
                unpack2(aI[r], ip[2 * r], ip[2 * r + 1]);
                unpack2(aF[r], fp[2 * r], fp[2 * r + 1]);
                unpack2(aG[r], gp[2 * r], gp[2 * r + 1]);
                unpack2(aO[r], op[2 * r], op[2 * r + 1]);
            }
#pragma unroll
            for (int r = 0; r < 4; r++) {
                const float ig = sigf(ip[r]);
                const float fg = sigf(fp[r]);
                const float gg = tanh_f(gp[r]);
                const float og = sigf(op[r]);
                c[r]  = fmaf(fg, c[r], ig * gg);
                hv[r] = og * tanh_f(c[r]);
            }
            *(float4*)&hsh[buf ^ 1][j][sl] =
                make_float4(hv[0], hv[1], hv[2], hv[3]);
        }
        __syncthreads();
    }
    // Final h1 lives in hsh buffer 0 (t=1023: buf=1, wrote buf^1=0).

    // ---- lstm2 single cell (zero initial state) + FC, fused ----
    for (int i = tid; i < H * H; i += NTH) {
        int k = i / H, jj = i - k * H;
        Wq[k][jj] = make_float4(W2ih[jj * H + k],
                                W2ih[(H + jj) * H + k],
                                W2ih[(2 * H + jj) * H + k],
                                W2ih[(3 * H + jj) * H + k]);
    }
    __syncthreads();

    float* h2s = &hsh[1][0][0];   // buffer 1 free; layout [j][slot], stride GP

    if (act) {
        const u64 cI = splat2(b2ih[j]         + b2hh[j]);
        const u64 cG = splat2(b2ih[2 * H + j] + b2hh[2 * H + j]);
        const u64 cO = splat2(b2ih[3 * H + j] + b2hh[3 * H + j]);
        u64 aI[2] = {cI, cI};
        u64 aG[2] = {cG, cG};
        u64 aO[2] = {cO, cO};   // f-gate skipped: c0 = 0
#pragma unroll 10
        for (int k = 0; k < H; k++) {
            const float4 w = Wq[k][j];
            const u64* hp = (const u64*)&hsh[0][k][sl];
            const u64 h01 = hp[0], h23 = hp[1];
            const u64 wI = splat2(w.x), wG = splat2(w.z), wO = splat2(w.w);
            ffma2(aI[0], h01, wI); ffma2(aI[1], h23, wI);
            ffma2(aG[0], h01, wG); ffma2(aG[1], h23, wG);
            ffma2(aO[0], h01, wO); ffma2(aO[1], h23, wO);
        }
        float ip[4], gp[4], op[4];
#pragma unroll
        for (int r = 0; r < 2; r++) {
            unpack2(aI[r], ip[2 * r], ip[2 * r + 1]);
            unpack2(aG[r], gp[2 * r], gp[2 * r + 1]);
            unpack2(aO[r], op[2 * r], op[2 * r + 1]);
        }
        float h2[4];
#pragma unroll
        for (int r = 0; r < 4; r++) {
            const float ig = sigf(ip[r]);
            const float gg = tanh_f(gp[r]);
            const float og = sigf(op[r]);
            h2[r] = og * tanh_f(ig * gg);   // c = i*g (f*c0 = 0)
        }
        *(float4*)&h2s[j * GP + sl] = make_float4(h2[0], h2[1], h2[2], h2[3]);
    }
    __syncthreads();

    if (tid < NBAT) {
        float s = fcb[0];
#pragma unroll 10
        for (int k = 0; k < H; k++)
            s = fmaf(h2s[k * GP + tid], __ldg(&fcW[k]), s);
        out[bbase + tid] = s;
    }
}

extern "C" void kernel_launch(void* const* d_in, const int* in_sizes, int n_in,
                              void* d_out, int out_size)
{
    const float* x     = (const float*)d_in[0];
    const float* w1ih  = (const float*)d_in[1];
    const float* w1hh  = (const float*)d_in[2];
    const float* b1ih  = (const float*)d_in[3];
    const float* b1hh  = (const float*)d_in[4];
    const float* w2ih  = (const float*)d_in[5];
    // d_in[6] = lstm2_Whh: unused (layer-2 initial state is zero)
    const float* b2ih  = (const float*)d_in[7];
    const float* b2hh  = (const float*)d_in[8];
    const float* fcW   = (const float*)d_in[9];
    const float* fcb   = (const float*)d_in[10];
    float* out = (float*)d_out;

    fused_lstm_kernel<<<BTOT / NBAT, NTH>>>(
        x, w1ih, w1hh, b1ih, b1hh, w2ih, b2ih, b2hh, fcW, fcb, out);
}

// round 17
// speedup vs baseline: 1.8793x; 1.2508x over previous
#include <cuda_runtime.h>

#define H 50
#define BTOT 2048
#define TLEN 1024
#define NBAT 16          // batches per block; grid = 128 -> 1 CTA/SM
#define NTH 256          // 8 warps = 2/SMSP
#define XCH 16
#define GP 20            // hsh row: 20 floats = 80B (odd*16B) -> conflict-light

typedef unsigned long long u64;

__device__ __forceinline__ u64 ffma2n(u64 a, u64 b, u64 c) {
    u64 d; asm("fma.rn.f32x2 %0, %1, %2, %3;" : "=l"(d) : "l"(a), "l"(b), "l"(c)); return d;
}
__device__ __forceinline__ void ffma2(u64 &d, u64 a, u64 b) {
    asm("fma.rn.f32x2 %0, %1, %2, %0;" : "+l"(d) : "l"(a), "l"(b));
}
__device__ __forceinline__ u64 splat2(float x) {
    u64 r; asm("mov.b64 %0, {%1, %1};" : "=l"(r) : "f"(x)); return r;
}
__device__ __forceinline__ void unpack2(u64 v, float &lo, float &hi) {
    asm("mov.b64 {%0, %1}, %2;" : "=f"(lo), "=f"(hi) : "l"(v));
}
__device__ __forceinline__ float tanh_f(float x) {
    float y; asm("tanh.approx.f32 %0, %1;" : "=f"(y) : "f"(x)); return y;
}
__device__ __forceinline__ float sigf(float x) {
    return fmaf(0.5f, tanh_f(0.5f * x), 0.5f);
}

// Fully fused lstm1 (1024 steps) + lstm2 cell + FC. One CTA/SM, 8 warps
// (2/SMSP so LDS latency + MUFU epilogue of one warp hide behind the other).
// Thread mapping: g = tid>>7 (batch octet), lid = tid&127, j = lid>>1
// (active j<50), hb = lid&1 -> batch slots sl = g*8 + hb*4 .. +3.
// Two lanes share each weight quad (16 distinct LDS.128 per warp = 256B).
// __launch_bounds__(NTH, 1): prevents the 64-reg cap that spilled in R15.
__global__ void __launch_bounds__(NTH, 1) fused_lstm_kernel(
    const float* __restrict__ x,
    const float* __restrict__ Wih,
    const float* __restrict__ Whh,
    const float* __restrict__ bih,
    const float* __restrict__ bhh,
    const float* __restrict__ W2ih,
    const float* __restrict__ b2ih,
    const float* __restrict__ b2hh,
    const float* __restrict__ fcW,
    const float* __restrict__ fcb,
    float* __restrict__ out)
{
    __shared__ __align__(16) float4 Wq[H][H];       // [k][j] = (Wi,Wf,Wg,Wo)[j][k]  40000B
    __shared__ __align__(16) float  hsh[2][H][GP];  // double-buffered h              8000B
    __shared__ __align__(16) float  xsh[XCH][NBAT]; // x chunk                        1024B

    const int tid = threadIdx.x;
    const int g   = tid >> 7;        // batch octet 0..1
    const int lid = tid & 127;
    const int j   = lid >> 1;        // 0..63, active if < 50
    const int hb  = lid & 1;         // batch half within octet
    const bool act = j < H;
    const int bbase = blockIdx.x * NBAT;
    const int sl = g * 8 + hb * 4;   // batch slot base: 0,4,8,12

    // Prepack Whh gate quads: Wq[k][jj] = 4 gate rows at column k
    for (int i = tid; i < H * H; i += NTH) {
        int k = i / H, jj = i - k * H;
        Wq[k][jj] = make_float4(Whh[jj * H + k],
                                Whh[(H + jj) * H + k],
                                Whh[(2 * H + jj) * H + k],
                                Whh[(3 * H + jj) * H + k]);
    }
    for (int i = tid; i < 2 * H * GP; i += NTH)
        (&hsh[0][0][0])[i] = 0.0f;

    u64 bI = 0, bF = 0, bG = 0, bO = 0, wiI = 0, wiF = 0, wiG = 0, wiO = 0;
    if (act) {
        bI = splat2(bih[j]         + bhh[j]);
        bF = splat2(bih[H + j]     + bhh[H + j]);
        bG = splat2(bih[2 * H + j] + bhh[2 * H + j]);
        bO = splat2(bih[3 * H + j] + bhh[3 * H + j]);
        wiI = splat2(Wih[j]);
        wiF = splat2(Wih[H + j]);
        wiG = splat2(Wih[2 * H + j]);
        wiO = splat2(Wih[3 * H + j]);
    }

    float c[4]  = {0.f, 0.f, 0.f, 0.f};
    float hv[4] = {0.f, 0.f, 0.f, 0.f};

    __syncthreads();

    for (int t = 0; t < TLEN; t++) {
        if ((t & (XCH - 1)) == 0) {
            // previous end-of-step barrier guarantees old xsh reads are done
            {
                int tc = tid >> 4, bl = tid & 15;   // 256 threads = 16x16 exactly
                xsh[tc][bl] = x[(bbase + bl) * TLEN + t + tc];
            }
            __syncthreads();
        }
        const int buf = t & 1;

        if (act) {
            const u64* xp = (const u64*)&xsh[t & (XCH - 1)][sl];
            const u64 x01 = xp[0], x23 = xp[1];

            u64 aI[2], aF[2], aG[2], aO[2];
            aI[0] = ffma2n(x01, wiI, bI); aI[1] = ffma2n(x23, wiI, bI);
            aF[0] = ffma2n(x01, wiF, bF); aF[1] = ffma2n(x23, wiF, bF);
            aG[0] = ffma2n(x01, wiG, bG); aG[1] = ffma2n(x23, wiG, bG);
            aO[0] = ffma2n(x01, wiO, bO); aO[1] = ffma2n(x23, wiO, bO);

#pragma unroll 10
            for (int k = 0; k < H; k++) {
                const float4 w = Wq[k][j];                      // LDS.128, 2 lanes share
                const u64* hp = (const u64*)&hsh[buf][k][sl];   // broadcast LDS.64 x2
                const u64 h01 = hp[0], h23 = hp[1];
                const u64 wI = splat2(w.x), wF = splat2(w.y);
                const u64 wG = splat2(w.z), wO = splat2(w.w);
                ffma2(aI[0], h01, wI); ffma2(aI[1], h23, wI);
                ffma2(aF[0], h01, wF); ffma2(aF[1], h23, wF);
                ffma2(aG[0], h01, wG); ffma2(aG[1], h23, wG);
                ffma2(aO[0], h01, wO); ffma2(aO[1], h23, wO);
            }

            float ip[4], fp[4], gp[4], op[4];
#pragma unroll
            for (int r = 0; r < 2; r++) {
                unpack2(aI[r], ip[2 * r], ip[2 * r + 1]);
                unpack2(aF[r], fp[2 * r], fp[2 * r + 1]);
                unpack2(aG[r], gp[2 * r], gp[2 * r + 1]);
                unpack2(aO[r], op[2 * r], op[2 * r + 1]);
            }
#pragma unroll
            for (int r = 0; r < 4; r++) {
                const float ig = sigf(ip[r]);
                const float fg = sigf(fp[r]);
                const float gg = tanh_f(gp[r]);
                const float og = sigf(op[r]);
                c[r]  = fmaf(fg, c[r], ig * gg);
                hv[r] = og * tanh_f(c[r]);
            }
            *(float4*)&hsh[buf ^ 1][j][sl] =
                make_float4(hv[0], hv[1], hv[2], hv[3]);
        }
        __syncthreads();
    }
    // Final h1 lives in hsh buffer 0 (t=1023: buf=1, wrote buf^1=0).

    // ---- lstm2 single cell (zero initial state) + FC, fused ----
    for (int i = tid; i < H * H; i += NTH) {
        int k = i / H, jj = i - k * H;
        Wq[k][jj] = make_float4(W2ih[jj * H + k],
                                W2ih[(H + jj) * H + k],
                                W2ih[(2 * H + jj) * H + k],
                                W2ih[(3 * H + jj) * H + k]);
    }
    __syncthreads();

    float* h2s = &hsh[1][0][0];   // buffer 1 free; layout [j][slot], stride GP

    if (act) {
        const u64 cI = splat2(b2ih[j]         + b2hh[j]);
        const u64 cG = splat2(b2ih[2 * H + j] + b2hh[2 * H + j]);
        const u64 cO = splat2(b2ih[3 * H + j] + b2hh[3 * H + j]);
        u64 aI[2] = {cI, cI};
        u64 aG[2] = {cG, cG};
        u64 aO[2] = {cO, cO};   // f-gate skipped: c0 = 0
#pragma unroll 10
        for (int k = 0; k < H; k++) {
            const float4 w = Wq[k][j];
            const u64* hp = (const u64*)&hsh[0][k][sl];
            const u64 h01 = hp[0], h23 = hp[1];
            const u64 wI = splat2(w.x), wG = splat2(w.z), wO = splat2(w.w);
            ffma2(aI[0], h01, wI); ffma2(aI[1], h23, wI);
            ffma2(aG[0], h01, wG); ffma2(aG[1], h23, wG);
            ffma2(aO[0], h01, wO); ffma2(aO[1], h23, wO);
        }
        float ip[4], gp[4], op[4];
#pragma unroll
        for (int r = 0; r < 2; r++) {
            unpack2(aI[r], ip[2 * r], ip[2 * r + 1]);
            unpack2(aG[r], gp[2 * r], gp[2 * r + 1]);
            unpack2(aO[r], op[2 * r], op[2 * r + 1]);
        }
        float h2[4];
#pragma unroll
        for (int r = 0; r < 4; r++) {
            const float ig = sigf(ip[r]);
            const float gg = tanh_f(gp[r]);
            const float og = sigf(op[r]);
            h2[r] = og * tanh_f(ig * gg);   // c = i*g (f*c0 = 0)
        }
        *(float4*)&h2s[j * GP + sl] = make_float4(h2[0], h2[1], h2[2], h2[3]);
    }
    __syncthreads();

    if (tid < NBAT) {
        float s = fcb[0];
#pragma unroll 10
        for (int k = 0; k < H; k++)
            s = fmaf(h2s[k * GP + tid], __ldg(&fcW[k]), s);
        out[bbase + tid] = s;
    }
}

extern "C" void kernel_launch(void* const* d_in, const int* in_sizes, int n_in,
                              void* d_out, int out_size)
{
    const float* x     = (const float*)d_in[0];
    const float* w1ih  = (const float*)d_in[1];
    const float* w1hh  = (const float*)d_in[2];
    const float* b1ih  = (const float*)d_in[3];
    const float* b1hh  = (const float*)d_in[4];
    const float* w2ih  = (const float*)d_in[5];
    // d_in[6] = lstm2_Whh: unused (layer-2 initial state is zero)
    const float* b2ih  = (const float*)d_in[7];
    const float* b2hh  = (const float*)d_in[8];
    const float* fcW   = (const float*)d_in[9];
    const float* fcb   = (const float*)d_in[10];
    float* out = (float*)d_out;

    fused_lstm_kernel<<<BTOT / NBAT, NTH>>>(
        x, w1ih, w1hh, b1ih, b1hh, w2ih, b2ih, b2hh, fcW, fcb, out);
}